// round 1
// baseline (speedup 1.0000x reference)
#include <cuda_runtime.h>

#define BATCH 2048
#define NH    512
#define H0C   256
#define H1C   256
#define TB    16   // samples per CTA tile

// Scratch (allocation-free rule: __device__ globals)
__device__ float g_top_prob[BATCH];
__device__ int   g_order[BATCH];
__device__ int   g_off[H0C + 1];

// ---------------------------------------------------------------------------
// Kernel 1: group samples by parent label (counts -> offsets -> scatter).
// Order within a group is nondeterministic but output is order-invariant.
// ---------------------------------------------------------------------------
__global__ void group_kernel(const int* __restrict__ parent) {
    __shared__ int cnt[H0C];
    __shared__ int cur[H0C];
    int tid = threadIdx.x;
    for (int i = tid; i < H0C; i += blockDim.x) cnt[i] = 0;
    __syncthreads();
    for (int b = tid; b < BATCH; b += blockDim.x)
        atomicAdd(&cnt[parent[b]], 1);
    __syncthreads();
    if (tid == 0) {
        int s = 0;
        for (int i = 0; i < H0C; i++) {
            cur[i] = s;
            g_off[i] = s;
            s += cnt[i];
        }
        g_off[H0C] = s;
    }
    __syncthreads();
    for (int b = tid; b < BATCH; b += blockDim.x) {
        int p = parent[b];
        int pos = atomicAdd(&cur[p], 1);
        g_order[pos] = b;
    }
}

// ---------------------------------------------------------------------------
// Kernel 2: top softmax. Each CTA: 16 samples x 256 classes, K=512.
// Thread j owns column j for all 16 rows (16 fp32 accumulators).
// W column loads are fully coalesced; input reads are smem broadcasts.
// ---------------------------------------------------------------------------
__global__ __launch_bounds__(256) void top_kernel(
    const float* __restrict__ inputs, const int* __restrict__ parent,
    const float* __restrict__ W, const float* __restrict__ bias)
{
    __shared__ float s_in[TB][NH];    // 32 KB
    __shared__ float s_log[TB][H0C];  // 16 KB
    int tid = threadIdx.x;
    int b0 = blockIdx.x * TB;

    // cooperative vectorized load of 16 input rows
    const float4* gin = (const float4*)(inputs + (size_t)b0 * NH);
    float4* sin4 = (float4*)&s_in[0][0];
    for (int i = tid; i < TB * NH / 4; i += 256) sin4[i] = gin[i];
    __syncthreads();

    float acc[TB];
#pragma unroll
    for (int s = 0; s < TB; s++) acc[s] = 0.f;

    const float* wc = W + tid;  // column j = tid
#pragma unroll 4
    for (int k = 0; k < NH; k++) {
        float w = wc[(size_t)k * H0C];
#pragma unroll
        for (int s = 0; s < TB; s++) acc[s] += w * s_in[s][k];
    }

    float bj = bias[tid];
#pragma unroll
    for (int s = 0; s < TB; s++) s_log[s][tid] = acc[s] + bj;
    __syncthreads();

    // softmax per row; 8 warps handle 2 rows each
    int wid = tid >> 5, lane = tid & 31;
    for (int r = wid; r < TB; r += 8) {
        float m = -1e30f;
#pragma unroll
        for (int j = lane; j < H0C; j += 32) m = fmaxf(m, s_log[r][j]);
#pragma unroll
        for (int o = 16; o > 0; o >>= 1) m = fmaxf(m, __shfl_xor_sync(0xffffffffu, m, o));
        float sum = 0.f;
#pragma unroll
        for (int j = lane; j < H0C; j += 32) sum += __expf(s_log[r][j] - m);
#pragma unroll
        for (int o = 16; o > 0; o >>= 1) sum += __shfl_xor_sync(0xffffffffu, sum, o);
        if (lane == 0) {
            int b = b0 + r;
            int p = parent[b];
            g_top_prob[b] = __expf(s_log[r][p] - m) / sum;
        }
    }
}

// ---------------------------------------------------------------------------
// Kernel 3: bottom softmax. One CTA per parent p; streams W[p] (512 KB) ONCE
// while computing logits for all samples in p's group (chunks of 16).
// Fuses the final top_prob * bottom_prob product.
// ---------------------------------------------------------------------------
__global__ __launch_bounds__(256) void bottom_kernel(
    const float* __restrict__ inputs, const int* __restrict__ labels,
    const float* __restrict__ Wb, const float* __restrict__ bb,
    float* __restrict__ out)
{
    int p = blockIdx.x;
    int start = g_off[p], end = g_off[p + 1];
    if (start == end) return;

    __shared__ float s_in[TB][NH];    // 32 KB
    __shared__ float s_log[TB][H1C];  // 16 KB
    int tid = threadIdx.x;

    const float* Wp = Wb + (size_t)p * NH * H1C;
    float biasj = bb[(size_t)p * H1C + tid];

    for (int c0 = start; c0 < end; c0 += TB) {
        int S = min(TB, end - c0);
        __syncthreads();  // previous chunk's softmax reads done

        // load S input rows (gathered via g_order)
        for (int i = tid; i < S * (NH / 4); i += 256) {
            int s = i / (NH / 4), q = i % (NH / 4);
            int b = g_order[c0 + s];
            ((float4*)&s_in[s][0])[q] = ((const float4*)(inputs + (size_t)b * NH))[q];
        }
        __syncthreads();

        float acc[TB];
#pragma unroll
        for (int s = 0; s < TB; s++) acc[s] = 0.f;

        const float* wc = Wp + tid;
#pragma unroll 4
        for (int k = 0; k < NH; k++) {
            float w = wc[(size_t)k * H1C];
#pragma unroll
            for (int s = 0; s < TB; s++) acc[s] += w * s_in[s][k];
        }

#pragma unroll
        for (int s = 0; s < TB; s++) s_log[s][tid] = acc[s] + biasj;
        __syncthreads();

        int wid = tid >> 5, lane = tid & 31;
        for (int r = wid; r < S; r += 8) {
            float m = -1e30f;
#pragma unroll
            for (int j = lane; j < H1C; j += 32) m = fmaxf(m, s_log[r][j]);
#pragma unroll
            for (int o = 16; o > 0; o >>= 1) m = fmaxf(m, __shfl_xor_sync(0xffffffffu, m, o));
            float sum = 0.f;
#pragma unroll
            for (int j = lane; j < H1C; j += 32) sum += __expf(s_log[r][j] - m);
#pragma unroll
            for (int o = 16; o > 0; o >>= 1) sum += __shfl_xor_sync(0xffffffffu, sum, o);
            if (lane == 0) {
                int b = g_order[c0 + r];
                int l = labels[b];
                out[b] = g_top_prob[b] * (__expf(s_log[r][l] - m) / sum);
            }
        }
    }
}

// ---------------------------------------------------------------------------
extern "C" void kernel_launch(void* const* d_in, const int* in_sizes, int n_in,
                              void* d_out, int out_size) {
    const float* inputs = (const float*)d_in[0];
    const int*   labels = (const int*)d_in[1];
    const int*   parent = (const int*)d_in[2];
    const float* topW   = (const float*)d_in[3];
    const float* topB   = (const float*)d_in[4];
    const float* botW   = (const float*)d_in[5];
    const float* botB   = (const float*)d_in[6];
    float* out = (float*)d_out;

    group_kernel<<<1, 256>>>(parent);
    top_kernel<<<BATCH / TB, 256>>>(inputs, parent, topW, topB);
    bottom_kernel<<<H0C, 256>>>(inputs, labels, botW, botB, out);
}

// round 2
// speedup vs baseline: 1.8883x; 1.8883x over previous
#include <cuda_runtime.h>
#include <cstdint>

#define BATCH 2048
#define NH    512
#define HC    256   // H0 == H1 == 256
#define TB    16

__device__ float g_top_prob[BATCH];
__device__ int   g_order[BATCH];
__device__ int   g_off[HC + 1];

// ---------------- PTX helpers: packed f32x2 FFMA path ----------------
__device__ __forceinline__ uint64_t pack2(float lo, float hi) {
    uint64_t d; asm("mov.b64 %0, {%1,%2};" : "=l"(d) : "f"(lo), "f"(hi)); return d;
}
__device__ __forceinline__ void unpack2(uint64_t v, float& lo, float& hi) {
    asm("mov.b64 {%0,%1}, %2;" : "=f"(lo), "=f"(hi) : "l"(v));
}
__device__ __forceinline__ uint64_t fma2(uint64_t a, uint64_t b, uint64_t c) {
    uint64_t d; asm("fma.rn.f32x2 %0, %1, %2, %3;" : "=l"(d) : "l"(a), "l"(b), "l"(c)); return d;
}
__device__ __forceinline__ void lds_v2u64(uint64_t& a, uint64_t& b, uint32_t addr) {
    asm volatile("ld.shared.v2.u64 {%0,%1}, [%2];" : "=l"(a), "=l"(b) : "r"(addr));
}

// ---------------------------------------------------------------------------
// Kernel 1: group samples by parent (histogram -> parallel scan -> scatter).
// ---------------------------------------------------------------------------
__global__ void group_kernel(const int* __restrict__ parent) {
    __shared__ int cnt[HC];
    __shared__ int incl[HC];
    __shared__ int cur[HC];
    int tid = threadIdx.x;
    cnt[tid] = 0;
    __syncthreads();
    for (int b = tid; b < BATCH; b += HC) atomicAdd(&cnt[parent[b]], 1);
    __syncthreads();
    int v = cnt[tid];
    incl[tid] = v;
    __syncthreads();
#pragma unroll
    for (int off = 1; off < HC; off <<= 1) {
        int t = (tid >= off) ? incl[tid - off] : 0;
        __syncthreads();
        incl[tid] += t;
        __syncthreads();
    }
    int excl = incl[tid] - v;
    g_off[tid] = excl;
    if (tid == HC - 1) g_off[HC] = BATCH;
    cur[tid] = excl;
    __syncthreads();
    for (int b = tid; b < BATCH; b += HC) {
        int p = parent[b];
        g_order[atomicAdd(&cur[p], 1)] = b;
    }
}

// ---------------------------------------------------------------------------
// Shared GEMM chunk: SA rows x 256 cols, K=512 split across two thread-halves
// (half h reduces k in [h*256, h*256+256)). Thread owns column j = tid&255.
// Inner loop: LDS.v2.u64 (4 input floats) + 2x fma.rn.f32x2 per row.
// Writes final logits (+bias) into s_log.
// ---------------------------------------------------------------------------
template <int SA>
__device__ __forceinline__ void gemm_chunk(
    const float* s_in,               // [TB][NH] flattened
    float* s_log,                    // [TB][HC] flattened
    const float* __restrict__ wc,    // W + j + k0*HC (this thread's column, this half)
    int j, int k0, int half, float biasj)
{
    uint64_t acc[SA];
#pragma unroll
    for (int s = 0; s < SA; s++) acc[s] = 0ull;

    uint32_t sbase = (uint32_t)__cvta_generic_to_shared(s_in + k0);

    // software-pipelined W column loads (prefetch distance 2 blocks of 4 k)
    float w0 = wc[0 * HC], w1 = wc[1 * HC], w2 = wc[2 * HC], w3 = wc[3 * HC];
    float p0 = wc[4 * HC], p1 = wc[5 * HC], p2 = wc[6 * HC], p3 = wc[7 * HC];

#pragma unroll 4
    for (int kb = 0; kb < NH / 2; kb += 4) {
        uint64_t wA = pack2(w0, w1);
        uint64_t wB = pack2(w2, w3);
        int kn = (kb + 8 < NH / 2) ? (kb + 8) : kb;  // guarded prefetch index
        const float* wn = wc + (size_t)kn * HC;
        w0 = p0; w1 = p1; w2 = p2; w3 = p3;
        p0 = wn[0 * HC]; p1 = wn[1 * HC]; p2 = wn[2 * HC]; p3 = wn[3 * HC];

        uint32_t a = sbase + kb * 4;
#pragma unroll
        for (int s = 0; s < SA; s++) {
            uint64_t v01, v23;
            lds_v2u64(v01, v23, a);
            acc[s] = fma2(v01, wA, acc[s]);
            acc[s] = fma2(v23, wB, acc[s]);
            a += NH * 4;
        }
    }

    float r[SA];
#pragma unroll
    for (int s = 0; s < SA; s++) {
        float lo, hi; unpack2(acc[s], lo, hi);
        r[s] = lo + hi;
    }
    if (half == 1) {
#pragma unroll
        for (int s = 0; s < SA; s++) s_log[s * HC + j] = r[s];
    }
    __syncthreads();
    if (half == 0) {
#pragma unroll
        for (int s = 0; s < SA; s++) s_log[s * HC + j] = r[s] + s_log[s * HC + j] + biasj;
    }
    __syncthreads();
}

// ---------------------------------------------------------------------------
// Kernel 2: top softmax. 128 CTAs x 16 samples, 512 threads (16 warps).
// ---------------------------------------------------------------------------
__global__ __launch_bounds__(512) void top_kernel(
    const float* __restrict__ inputs, const int* __restrict__ parent,
    const float* __restrict__ W, const float* __restrict__ bias)
{
    __shared__ float s_in[TB * NH];   // 32 KB
    __shared__ float s_log[TB * HC];  // 16 KB
    int tid = threadIdx.x;
    int j = tid & (HC - 1);
    int half = tid >> 8;
    int k0 = half * (NH / 2);
    int b0 = blockIdx.x * TB;

    const float4* gin = (const float4*)(inputs + (size_t)b0 * NH);
    float4* s4 = (float4*)s_in;
    for (int i = tid; i < TB * NH / 4; i += 512) s4[i] = gin[i];
    __syncthreads();

    float bj = bias[j];
    gemm_chunk<TB>(s_in, s_log, W + j + (size_t)k0 * HC, j, k0, half, bj);

    // softmax: 16 warps, one row each
    int wid = tid >> 5, lane = tid & 31;
    const float* row = s_log + wid * HC;
    float m = -1e30f;
#pragma unroll
    for (int c = lane; c < HC; c += 32) m = fmaxf(m, row[c]);
#pragma unroll
    for (int o = 16; o > 0; o >>= 1) m = fmaxf(m, __shfl_xor_sync(0xffffffffu, m, o));
    float sum = 0.f;
#pragma unroll
    for (int c = lane; c < HC; c += 32) sum += __expf(row[c] - m);
#pragma unroll
    for (int o = 16; o > 0; o >>= 1) sum += __shfl_xor_sync(0xffffffffu, sum, o);
    if (lane == 0) {
        int b = b0 + wid;
        int p = parent[b];
        g_top_prob[b] = __expf(row[p] - m) / sum;
    }
}

// ---------------------------------------------------------------------------
// Kernel 3: bottom softmax. One CTA per parent; streams W[p] once per chunk;
// accumulator count templated on actual group size to avoid wasted FFMA.
// ---------------------------------------------------------------------------
__global__ __launch_bounds__(512) void bottom_kernel(
    const float* __restrict__ inputs, const int* __restrict__ labels,
    const float* __restrict__ Wb, const float* __restrict__ bb,
    float* __restrict__ out)
{
    int p = blockIdx.x;
    int start = g_off[p], end = g_off[p + 1];
    if (start == end) return;

    __shared__ float s_in[TB * NH];
    __shared__ float s_log[TB * HC];
    int tid = threadIdx.x;
    int j = tid & (HC - 1);
    int half = tid >> 8;
    int k0 = half * (NH / 2);
    int wid = tid >> 5, lane = tid & 31;

    const float* Wp = Wb + (size_t)p * NH * HC;
    const float* wc = Wp + j + (size_t)k0 * HC;
    float biasj = bb[(size_t)p * HC + j];

    for (int c0 = start; c0 < end; c0 += TB) {
        int S = min(TB, end - c0);
        __syncthreads();  // protect s_log/s_in from previous iteration readers

        // gather S input rows
        for (int i = tid; i < S * (NH / 4); i += 512) {
            int s = i >> 7, q = i & 127;
            int b = g_order[c0 + s];
            ((float4*)(s_in + s * NH))[q] = ((const float4*)(inputs + (size_t)b * NH))[q];
        }
        __syncthreads();

        switch ((S + 3) >> 2) {
            case 1:  gemm_chunk<4>(s_in, s_log, wc, j, k0, half, biasj); break;
            case 2:  gemm_chunk<8>(s_in, s_log, wc, j, k0, half, biasj); break;
            case 3:  gemm_chunk<12>(s_in, s_log, wc, j, k0, half, biasj); break;
            default: gemm_chunk<16>(s_in, s_log, wc, j, k0, half, biasj); break;
        }

        if (wid < S) {
            const float* row = s_log + wid * HC;
            float m = -1e30f;
#pragma unroll
            for (int c = lane; c < HC; c += 32) m = fmaxf(m, row[c]);
#pragma unroll
            for (int o = 16; o > 0; o >>= 1) m = fmaxf(m, __shfl_xor_sync(0xffffffffu, m, o));
            float sum = 0.f;
#pragma unroll
            for (int c = lane; c < HC; c += 32) sum += __expf(row[c] - m);
#pragma unroll
            for (int o = 16; o > 0; o >>= 1) sum += __shfl_xor_sync(0xffffffffu, sum, o);
            if (lane == 0) {
                int b = g_order[c0 + wid];
                int l = labels[b];
                out[b] = g_top_prob[b] * (__expf(row[l] - m) / sum);
            }
        }
    }
}

// ---------------------------------------------------------------------------
extern "C" void kernel_launch(void* const* d_in, const int* in_sizes, int n_in,
                              void* d_out, int out_size) {
    const float* inputs = (const float*)d_in[0];
    const int*   labels = (const int*)d_in[1];
    const int*   parent = (const int*)d_in[2];
    const float* topW   = (const float*)d_in[3];
    const float* topB   = (const float*)d_in[4];
    const float* botW   = (const float*)d_in[5];
    const float* botB   = (const float*)d_in[6];
    float* out = (float*)d_out;

    group_kernel<<<1, HC>>>(parent);
    top_kernel<<<BATCH / TB, 512>>>(inputs, parent, topW, topB);
    bottom_kernel<<<HC, 512>>>(inputs, labels, botW, botB, out);
}

// round 3
// speedup vs baseline: 2.4458x; 1.2953x over previous
#include <cuda_runtime.h>
#include <cstdint>

#define BATCH 2048
#define NH    512
#define HC    256

__device__ float g_top_prob[BATCH];

// ---------------- packed f32x2 helpers ----------------
__device__ __forceinline__ uint64_t pack2(float lo, float hi) {
    uint64_t d; asm("mov.b64 %0, {%1,%2};" : "=l"(d) : "f"(lo), "f"(hi)); return d;
}
__device__ __forceinline__ void unpack2(uint64_t v, float& lo, float& hi) {
    asm("mov.b64 {%0,%1}, %2;" : "=f"(lo), "=f"(hi) : "l"(v));
}
__device__ __forceinline__ uint64_t fma2(uint64_t a, uint64_t b, uint64_t c) {
    uint64_t d; asm("fma.rn.f32x2 %0, %1, %2, %3;" : "=l"(d) : "l"(a), "l"(b), "l"(c)); return d;
}
__device__ __forceinline__ void lds_v2u64(uint64_t& a, uint64_t& b, uint32_t addr) {
    asm volatile("ld.shared.v2.u64 {%0,%1}, [%2];" : "=l"(a), "=l"(b) : "r"(addr));
}

// ---------------------------------------------------------------------------
// GEMM body: SA rows x 256 cols, K split in halves of 256 across thread halves.
// Thread owns column j for its k-half. W streamed via ping-pong register
// prefetch (distance 2 blocks of 8 k). Inner: LDS.v2.u64 + fma.rn.f32x2.
// Writes logits (+bias) to s_log.
// ---------------------------------------------------------------------------
template <int SA>
__device__ __forceinline__ void gemm_body(
    const float* s_in_k,             // s_in + k0 (this half's k origin)
    float* s_log,                    // [SA][HC]
    const float* __restrict__ wc,    // W + j + k0*HC
    int j, int half, float biasj)
{
    uint64_t acc[SA];
#pragma unroll
    for (int s = 0; s < SA; s++) acc[s] = 0ull;

    uint32_t sb = (uint32_t)__cvta_generic_to_shared(s_in_k);

    const int NBLK = (NH / 2) / 8;   // 32 blocks of 8 k
    float A[8], B[8];
#pragma unroll
    for (int i = 0; i < 8; i++) A[i] = wc[(size_t)i * HC];
#pragma unroll
    for (int i = 0; i < 8; i++) B[i] = wc[(size_t)(8 + i) * HC];

    for (int ib = 0; ib < NBLK; ib += 2) {
        // ---- block ib (buffer A), prefetch A <- block ib+2 ----
        {
            uint64_t wA = pack2(A[0], A[1]), wB = pack2(A[2], A[3]);
            uint64_t wC = pack2(A[4], A[5]), wD = pack2(A[6], A[7]);
            int ip = (ib + 2 < NBLK) ? (ib + 2) : ib;
            const float* wp = wc + (size_t)ip * 8 * HC;
#pragma unroll
            for (int i = 0; i < 8; i++) A[i] = wp[(size_t)i * HC];

            uint32_t a = sb + ib * 32;
#pragma unroll
            for (int s = 0; s < SA; s++) {
                uint64_t v01, v23, v45, v67;
                lds_v2u64(v01, v23, a);
                lds_v2u64(v45, v67, a + 16);
                acc[s] = fma2(v01, wA, acc[s]);
                acc[s] = fma2(v23, wB, acc[s]);
                acc[s] = fma2(v45, wC, acc[s]);
                acc[s] = fma2(v67, wD, acc[s]);
                a += NH * 4;
            }
        }
        // ---- block ib+1 (buffer B), prefetch B <- block ib+3 ----
        {
            uint64_t wA = pack2(B[0], B[1]), wB = pack2(B[2], B[3]);
            uint64_t wC = pack2(B[4], B[5]), wD = pack2(B[6], B[7]);
            int ip = (ib + 3 < NBLK) ? (ib + 3) : (ib + 1);
            const float* wp = wc + (size_t)ip * 8 * HC;
#pragma unroll
            for (int i = 0; i < 8; i++) B[i] = wp[(size_t)i * HC];

            uint32_t a = sb + (ib + 1) * 32;
#pragma unroll
            for (int s = 0; s < SA; s++) {
                uint64_t v01, v23, v45, v67;
                lds_v2u64(v01, v23, a);
                lds_v2u64(v45, v67, a + 16);
                acc[s] = fma2(v01, wA, acc[s]);
                acc[s] = fma2(v23, wB, acc[s]);
                acc[s] = fma2(v45, wC, acc[s]);
                acc[s] = fma2(v67, wD, acc[s]);
                a += NH * 4;
            }
        }
    }

    float r[SA];
#pragma unroll
    for (int s = 0; s < SA; s++) {
        float lo, hi; unpack2(acc[s], lo, hi);
        r[s] = lo + hi;
    }
    if (half == 1) {
#pragma unroll
        for (int s = 0; s < SA; s++) s_log[s * HC + j] = r[s];
    }
    __syncthreads();
    if (half == 0) {
#pragma unroll
        for (int s = 0; s < SA; s++) s_log[s * HC + j] = r[s] + s_log[s * HC + j] + biasj;
    }
    __syncthreads();
}

__device__ __forceinline__ void softmax_row_prob(
    const float* row, int lane, float& m_out, float& sum_out)
{
    float m = -1e30f;
#pragma unroll
    for (int c = lane; c < HC; c += 32) m = fmaxf(m, row[c]);
#pragma unroll
    for (int o = 16; o > 0; o >>= 1) m = fmaxf(m, __shfl_xor_sync(0xffffffffu, m, o));
    float sum = 0.f;
#pragma unroll
    for (int c = lane; c < HC; c += 32) sum += __expf(row[c] - m);
#pragma unroll
    for (int o = 16; o > 0; o >>= 1) sum += __shfl_xor_sync(0xffffffffu, sum, o);
    m_out = m; sum_out = sum;
}

// ---------------------------------------------------------------------------
// Top kernel: 128 CTAs x 16 samples, 512 threads. W_top stays L2-resident.
// ---------------------------------------------------------------------------
#define TTB 16
__global__ __launch_bounds__(512, 1) void top_kernel(
    const float* __restrict__ inputs, const int* __restrict__ parent,
    const float* __restrict__ W, const float* __restrict__ bias)
{
    __shared__ float s_in[TTB * NH];   // 32 KB
    __shared__ float s_log[TTB * HC];  // 16 KB
    int tid = threadIdx.x;
    int j = tid & (HC - 1);
    int half = tid >> 8;
    int k0 = half * (NH / 2);
    int b0 = blockIdx.x * TTB;

    const float4* gin = (const float4*)(inputs + (size_t)b0 * NH);
    float4* s4 = (float4*)s_in;
#pragma unroll
    for (int i = 0; i < TTB * NH / 4 / 512; i++) s4[tid + i * 512] = gin[tid + i * 512];
    __syncthreads();

    gemm_body<TTB>(s_in + k0, s_log, W + j + (size_t)k0 * HC, j, half, bias[j]);

    int wid = tid >> 5, lane = tid & 31;
    const float* row = s_log + wid * HC;
    float m, sum;
    softmax_row_prob(row, lane, m, sum);
    if (lane == 0) {
        int b = b0 + wid;
        int p = parent[b];
        g_top_prob[b] = __expf(row[p] - m) / sum;
    }
}

// ---------------------------------------------------------------------------
// Bottom kernel: one CTA per parent. Self-groups by scanning parent[] (L2-hot),
// then streams W[p] (512KB) from DRAM once per chunk of 8 samples.
// ---------------------------------------------------------------------------
#define BTB 8
#define IDXCAP 1024
__global__ __launch_bounds__(512, 2) void bottom_kernel(
    const float* __restrict__ inputs, const int* __restrict__ parent,
    const int* __restrict__ labels,
    const float* __restrict__ Wb, const float* __restrict__ bb,
    float* __restrict__ out)
{
    __shared__ float s_in[BTB * NH];   // 16 KB
    __shared__ float s_log[BTB * HC];  // 8 KB
    __shared__ int   s_idx[IDXCAP];    // 4 KB
    __shared__ int   s_cnt;

    int p = blockIdx.x;
    int tid = threadIdx.x;
    int j = tid & (HC - 1);
    int half = tid >> 8;
    int k0 = half * (NH / 2);
    int wid = tid >> 5, lane = tid & 31;

    if (tid == 0) s_cnt = 0;
    __syncthreads();
    for (int i = tid; i < BATCH; i += 512) {
        if (parent[i] == p) {
            int q = atomicAdd(&s_cnt, 1);
            if (q < IDXCAP) s_idx[q] = i;
        }
    }
    __syncthreads();
    int S_total = min(s_cnt, IDXCAP);
    if (S_total == 0) return;

    const float* wc = Wb + (size_t)p * NH * HC + j + (size_t)k0 * HC;
    float biasj = bb[(size_t)p * HC + j];

    for (int c0 = 0; c0 < S_total; c0 += BTB) {
        int S = min(BTB, S_total - c0);
        __syncthreads();  // prev softmax done reading s_log

        for (int i = tid; i < S * (NH / 4); i += 512) {
            int s = i >> 7, q = i & 127;
            int b = s_idx[c0 + s];
            ((float4*)(s_in + s * NH))[q] = ((const float4*)(inputs + (size_t)b * NH))[q];
        }
        __syncthreads();

        if (S <= 4) gemm_body<4>(s_in + k0, s_log, wc, j, half, biasj);
        else        gemm_body<8>(s_in + k0, s_log, wc, j, half, biasj);

        if (wid < S) {
            const float* row = s_log + wid * HC;
            float m, sum;
            softmax_row_prob(row, lane, m, sum);
            if (lane == 0) {
                int b = s_idx[c0 + wid];
                int l = labels[b];
                out[b] = g_top_prob[b] * (__expf(row[l] - m) / sum);
            }
        }
    }
}

// ---------------------------------------------------------------------------
extern "C" void kernel_launch(void* const* d_in, const int* in_sizes, int n_in,
                              void* d_out, int out_size) {
    const float* inputs = (const float*)d_in[0];
    const int*   labels = (const int*)d_in[1];
    const int*   parent = (const int*)d_in[2];
    const float* topW   = (const float*)d_in[3];
    const float* topB   = (const float*)d_in[4];
    const float* botW   = (const float*)d_in[5];
    const float* botB   = (const float*)d_in[6];
    float* out = (float*)d_out;

    top_kernel<<<BATCH / TTB, 512>>>(inputs, parent, topW, topB);
    bottom_kernel<<<HC, 512>>>(inputs, parent, labels, botW, botB, out);
}